// round 5
// baseline (speedup 1.0000x reference)
#include <cuda_runtime.h>

// x: (4096, 8192) fp32, row-major. p = x[:, :4096], q = x[:, 4096:].
// out[:, :4096] = p
// out[:, 4096:] = weight[row] * selu(p) + q

#define SIZE    4096
#define HALF4   (SIZE / 4)          // 1024 float4 per half-row
#define ROW4    (2 * SIZE / 4)      // 2048 float4 per full x row
#define TOTAL4  (SIZE * HALF4)      // 4,194,304 float4-pairs

__device__ __forceinline__ float selu_f(float v) {
    const float SCALE = 1.0507009873554804934193349852946f;
    const float ALPHA = 1.6732632423543772848170429916717f;
    float neg = SCALE * ALPHA * (__expf(fminf(v, 0.0f)) - 1.0f);
    float pos = SCALE * v;
    return v > 0.0f ? pos : neg;
}

__device__ __forceinline__ float4 fuse4(float4 p, float4 q, float w) {
    float4 r;
    r.x = fmaf(w, selu_f(p.x), q.x);
    r.y = fmaf(w, selu_f(p.y), q.y);
    r.z = fmaf(w, selu_f(p.z), q.z);
    r.w = fmaf(w, selu_f(p.w), q.w);
    return r;
}

__global__ __launch_bounds__(256) void selu_fuse_kernel(
    const float4* __restrict__ x,
    const float*  __restrict__ weight,
    float4*       __restrict__ out)
{
    // Each block owns 512 consecutive float4-pair indices, split into two
    // coalesced slabs so each warp's accesses are contiguous 128B segments.
    int base = blockIdx.x * 512 + threadIdx.x;
    int i0 = base;            // slab 0
    int i1 = base + 256;      // slab 1

    int row0  = i0 >> 10, col0 = i0 & 1023;
    int row1  = i1 >> 10, col1 = i1 & 1023;

    long long off0 = (long long)row0 * ROW4 + col0;
    long long off1 = (long long)row1 * ROW4 + col1;

    // Front-batch all 4 independent 16B loads (MLP=4), streaming policy.
    float4 p0 = __ldcs(x + off0);
    float4 p1 = __ldcs(x + off1);
    float4 q0 = __ldcs(x + off0 + HALF4);
    float4 q1 = __ldcs(x + off1 + HALF4);

    float w0 = __ldg(weight + row0);
    float w1 = __ldg(weight + row1);

    float4 r0 = fuse4(p0, q0, w0);
    float4 r1 = fuse4(p1, q1, w1);

    __stcs(out + off0,         p0);
    __stcs(out + off1,         p1);
    __stcs(out + off0 + HALF4, r0);
    __stcs(out + off1 + HALF4, r1);
}

extern "C" void kernel_launch(void* const* d_in, const int* in_sizes, int n_in,
                              void* d_out, int out_size)
{
    const float4* x = (const float4*)d_in[0];
    const float*  w = (const float*)d_in[1];
    float4* out = (float4*)d_out;

    const int block = 256;
    const int grid  = TOTAL4 / (block * 2);   // 8192 blocks, 2 pairs/thread

    selu_fuse_kernel<<<grid, block>>>(x, w, out);
}